// round 6
// baseline (speedup 1.0000x reference)
#include <cuda_runtime.h>

#define TPB 256
#define SPT 2

typedef unsigned long long ull;

__constant__ ull cw1[26 * 8];   // (w1[i][2j], w1[i][2j+1]) packed pairs

__device__ __forceinline__ ull pack2(float lo, float hi) {
    ull r;
    asm("mov.b64 %0, {%1, %2};" : "=l"(r) : "f"(lo), "f"(hi));
    return r;
}
__device__ __forceinline__ void unpack2(ull v, float& lo, float& hi) {
    asm("mov.b64 {%0, %1}, %2;" : "=f"(lo), "=f"(hi) : "l"(v));
}
__device__ __forceinline__ ull fma2(ull a, ull b, ull c) {
    ull d;
    asm("fma.rn.f32x2 %0, %1, %2, %3;" : "=l"(d) : "l"(a), "l"(b), "l"(c));
    return d;
}
__device__ __forceinline__ float getc(float4 v, int k) {
    return (k == 0) ? v.x : (k == 1) ? v.y : (k == 2) ? v.z : v.w;
}

__global__ __launch_bounds__(TPB, 2) void dlrm_kernel(
    const int*    __restrict__ user_id,
    const int*    __restrict__ item_id,
    const int*    __restrict__ cat_id,
    const float2* __restrict__ dense,
    const float4* __restrict__ user_t,   // [NUM_USERS, 8] as [., 2] float4
    const float4* __restrict__ item_t,
    const float4* __restrict__ cat_t,
    const float*  __restrict__ b1,
    const float*  __restrict__ w2,
    const float*  __restrict__ b2,
    float*        __restrict__ out,
    int batch)
{
    const int lane = threadIdx.x & 31;
    const int h    = lane & 1;           // which 16B half this lane fetches
    const bool odd = (h != 0);

    const int s0 = blockIdx.x * (TPB * SPT) + threadIdx.x;
    if (s0 >= batch) return;  // never taken: batch % (TPB*SPT) == 0

    // ---- coalesced id/dense loads ----
    int ids[3][SPT];
    float2 dn[SPT];
#pragma unroll
    for (int s = 0; s < SPT; s++) {
        int idx = s0 + s * TPB;
        ids[0][s] = user_id[idx];
        ids[1][s] = item_id[idx];
        ids[2][s] = cat_id[idx];
        dn[s]     = dense[idx];
    }

    // ---- cooperative pairwise gather, all 12 loads in flight (MLP=12).
    // Lanes 2k/2k+1 each fetch one 16B half of BOTH rows of the lane pair:
    // every 128B line is touched by exactly one instruction.
    float4 rA[6], rB[6];
#pragma unroll
    for (int g = 0; g < 6; g++) {
        const int T = g >> 1, s = g & 1;
        const float4* tab = (T == 0) ? user_t : (T == 1) ? item_t : cat_t;
        int idE = __shfl_sync(0xFFFFFFFFu, ids[T][s], lane & ~1);
        int idO = __shfl_sync(0xFFFFFFFFu, ids[T][s], lane | 1);
        rA[g] = tab[2 * (long)idE + h];
        rB[g] = tab[2 * (long)idO + h];
    }

    // ---- layer 1 accumulators: acc[s][jp] = (h[2jp], h[2jp+1]) ----
    ull acc[SPT][8];
#pragma unroll
    for (int j = 0; j < 8; j++) {
        ull b = __ldg((const ull*)b1 + j);   // uniform, 1 wf each
#pragma unroll
        for (int s = 0; s < SPT; s++) acc[s][j] = b;
    }

#pragma unroll
    for (int T = 0; T < 3; T++) {
        // exchange halves within lane pairs: lo[s]=f[8T..8T+3], hi[s]=f[8T+4..8T+7]
        float4 lo[SPT], hi[SPT];
#pragma unroll
        for (int s = 0; s < SPT; s++) {
            const int g = T * 2 + s;
            float4 send = odd ? rA[g] : rB[g];
            float4 own  = odd ? rB[g] : rA[g];
            float4 recv;
            recv.x = __shfl_xor_sync(0xFFFFFFFFu, send.x, 1);
            recv.y = __shfl_xor_sync(0xFFFFFFFFu, send.y, 1);
            recv.z = __shfl_xor_sync(0xFFFFFFFFu, send.z, 1);
            recv.w = __shfl_xor_sync(0xFFFFFFFFu, send.w, 1);
            lo[s] = odd ? recv : own;
            hi[s] = odd ? own  : recv;
        }
        // FMA block: weights from __constant__ (off the L1 path)
#pragma unroll
        for (int ii = 0; ii < 8; ii++) {
            const int i = T * 8 + ii;
            ull w0 = cw1[i * 8 + 0], w1v = cw1[i * 8 + 1];
            ull w2v = cw1[i * 8 + 2], w3 = cw1[i * 8 + 3];
            ull w4 = cw1[i * 8 + 4], w5 = cw1[i * 8 + 5];
            ull w6 = cw1[i * 8 + 6], w7 = cw1[i * 8 + 7];
#pragma unroll
            for (int s = 0; s < SPT; s++) {
                float fv = (ii < 4) ? getc(lo[s], ii) : getc(hi[s], ii - 4);
                ull p = pack2(fv, fv);
                acc[s][0] = fma2(p, w0,  acc[s][0]);
                acc[s][1] = fma2(p, w1v, acc[s][1]);
                acc[s][2] = fma2(p, w2v, acc[s][2]);
                acc[s][3] = fma2(p, w3,  acc[s][3]);
                acc[s][4] = fma2(p, w4,  acc[s][4]);
                acc[s][5] = fma2(p, w5,  acc[s][5]);
                acc[s][6] = fma2(p, w6,  acc[s][6]);
                acc[s][7] = fma2(p, w7,  acc[s][7]);
            }
        }
    }

    // ---- dense features i = 24, 25 ----
#pragma unroll
    for (int ii = 0; ii < 2; ii++) {
        const int i = 24 + ii;
        ull w0 = cw1[i * 8 + 0], w1v = cw1[i * 8 + 1];
        ull w2v = cw1[i * 8 + 2], w3 = cw1[i * 8 + 3];
        ull w4 = cw1[i * 8 + 4], w5 = cw1[i * 8 + 5];
        ull w6 = cw1[i * 8 + 6], w7 = cw1[i * 8 + 7];
#pragma unroll
        for (int s = 0; s < SPT; s++) {
            float fv = (ii == 0) ? dn[s].x : dn[s].y;
            ull p = pack2(fv, fv);
            acc[s][0] = fma2(p, w0,  acc[s][0]);
            acc[s][1] = fma2(p, w1v, acc[s][1]);
            acc[s][2] = fma2(p, w2v, acc[s][2]);
            acc[s][3] = fma2(p, w3,  acc[s][3]);
            acc[s][4] = fma2(p, w4,  acc[s][4]);
            acc[s][5] = fma2(p, w5,  acc[s][5]);
            acc[s][6] = fma2(p, w6,  acc[s][6]);
            acc[s][7] = fma2(p, w7,  acc[s][7]);
        }
    }

    // ---- relu + layer 2 + sigmoid (w2/b2 via uniform LDG) ----
    float w2r[16];
#pragma unroll
    for (int k = 0; k < 16; k++) w2r[k] = __ldg(w2 + k);
    const float sb2v = __ldg(b2);
#pragma unroll
    for (int s = 0; s < SPT; s++) {
        float l = sb2v;
#pragma unroll
        for (int j = 0; j < 8; j++) {
            float h0, h1;
            unpack2(acc[s][j], h0, h1);
            l = fmaf(fmaxf(h0, 0.0f), w2r[2 * j],     l);
            l = fmaf(fmaxf(h1, 0.0f), w2r[2 * j + 1], l);
        }
        float e = __expf(-l);
        out[s0 + s * TPB] = __fdividef(1.0f, 1.0f + e);
    }
}

extern "C" void kernel_launch(void* const* d_in, const int* in_sizes, int n_in,
                              void* d_out, int out_size) {
    const int*    user_id = (const int*)d_in[0];
    const int*    item_id = (const int*)d_in[1];
    const int*    cat_id  = (const int*)d_in[2];
    const float2* dense   = (const float2*)d_in[3];
    const float4* user_t  = (const float4*)d_in[4];
    const float4* item_t  = (const float4*)d_in[5];
    const float4* cat_t   = (const float4*)d_in[6];
    const float*  w1      = (const float*)d_in[7];
    const float*  b1      = (const float*)d_in[8];
    const float*  w2      = (const float*)d_in[9];
    const float*  b2      = (const float*)d_in[10];
    float*        out     = (float*)d_out;

    // Single graph-capturable D2D memcpy node: only w1 lives in __constant__.
    cudaMemcpyToSymbolAsync(cw1, w1, 26 * 16 * sizeof(float), 0,
                            cudaMemcpyDeviceToDevice, 0);

    const int batch = in_sizes[0];
    const int per_block = TPB * SPT;
    const int blocks = (batch + per_block - 1) / per_block;

    dlrm_kernel<<<blocks, TPB>>>(user_id, item_id, cat_id, dense,
                                 user_t, item_t, cat_t,
                                 b1, w2, b2, out, batch);
}

// round 7
// speedup vs baseline: 1.5966x; 1.5966x over previous
#include <cuda_runtime.h>

#define TPB 128
#define SPT 4

typedef unsigned long long ull;

__constant__ ull cw1[26 * 8];   // (w1[i][2j], w1[i][2j+1]) packed pairs

__device__ __forceinline__ ull pack2(float lo, float hi) {
    ull r;
    asm("mov.b64 %0, {%1, %2};" : "=l"(r) : "f"(lo), "f"(hi));
    return r;
}
__device__ __forceinline__ void unpack2(ull v, float& lo, float& hi) {
    asm("mov.b64 {%0, %1}, %2;" : "=f"(lo), "=f"(hi) : "l"(v));
}
__device__ __forceinline__ ull fma2(ull a, ull b, ull c) {
    ull d;
    asm("fma.rn.f32x2 %0, %1, %2, %3;" : "=l"(d) : "l"(a), "l"(b), "l"(c));
    return d;
}
__device__ __forceinline__ float getc(float4 v, int k) {
    return (k == 0) ? v.x : (k == 1) ? v.y : (k == 2) ? v.z : v.w;
}

__global__ __launch_bounds__(TPB, 3) void dlrm_kernel(
    const int*    __restrict__ user_id,
    const int*    __restrict__ item_id,
    const int*    __restrict__ cat_id,
    const float2* __restrict__ dense,
    const float4* __restrict__ user_t,   // [NUM_USERS, 8] as [., 2] float4
    const float4* __restrict__ item_t,
    const float4* __restrict__ cat_t,
    const float*  __restrict__ b1,
    const float*  __restrict__ w2,
    const float*  __restrict__ b2,
    float*        __restrict__ out,
    int batch)
{
    const int lane = threadIdx.x & 31;
    const int h    = lane & 1;           // which 16B half this lane fetches
    const bool odd = (h != 0);

    const int blockBase = blockIdx.x * (TPB * SPT);
    const int s0 = blockBase + threadIdx.x;
    if (s0 >= batch) return;  // never taken: batch % (TPB*SPT) == 0
    const int warpBase = blockBase + (threadIdx.x & ~31);  // lane0/s0 sample idx

    // ---- coalesced dense loads (own samples) ----
    float2 dn[SPT];
#pragma unroll
    for (int s = 0; s < SPT; s++) dn[s] = dense[s0 + s * TPB];

    // ---- cooperative pairwise gather, all 12 row loads in flight.
    // Fetching lane reads the PAIR's ids directly (coalesced, pair-duplicated
    // -> 1 wavefront) instead of shfl-routing: shorter LDG->LDG chain.
    // Lanes 2k/2k+1 each fetch one 16B half of BOTH rows of the lane pair:
    // every 128B line is touched by exactly one instruction.
    float4 rA[12], rB[12];   // rA: even owner's row half, rB: odd owner's
#pragma unroll
    for (int g = 0; g < 12; g++) {
        const int T = g >> 2, s = g & 3;
        const int* __restrict__ idp = (T == 0) ? user_id : (T == 1) ? item_id : cat_id;
        const float4* __restrict__ tab = (T == 0) ? user_t : (T == 1) ? item_t : cat_t;
        const int ge = warpBase + s * TPB + (lane & ~1);
        int idE = idp[ge];
        int idO = idp[ge + 1];
        rA[g] = tab[2 * (long)idE + h];
        rB[g] = tab[2 * (long)idO + h];
    }

    // ---- layer 1 accumulators: acc[s][jp] = (h[2jp], h[2jp+1]) ----
    ull acc[SPT][8];
#pragma unroll
    for (int j = 0; j < 8; j++) {
        ull b = __ldg((const ull*)b1 + j);   // uniform
#pragma unroll
        for (int s = 0; s < SPT; s++) acc[s][j] = b;
    }

#pragma unroll
    for (int T = 0; T < 3; T++) {
        // exchange halves within lane pairs: lo[s]=f[8T..8T+3], hi[s]=f[8T+4..8T+7]
        float4 lo[SPT], hi[SPT];
#pragma unroll
        for (int s = 0; s < SPT; s++) {
            const int g = T * 4 + s;
            float4 send = odd ? rA[g] : rB[g];
            float4 own  = odd ? rB[g] : rA[g];
            float4 recv;
            recv.x = __shfl_xor_sync(0xFFFFFFFFu, send.x, 1);
            recv.y = __shfl_xor_sync(0xFFFFFFFFu, send.y, 1);
            recv.z = __shfl_xor_sync(0xFFFFFFFFu, send.z, 1);
            recv.w = __shfl_xor_sync(0xFFFFFFFFu, send.w, 1);
            lo[s] = odd ? recv : own;
            hi[s] = odd ? own  : recv;
        }
        // FMA block: weights from __constant__ (off the L1 path)
#pragma unroll
        for (int ii = 0; ii < 8; ii++) {
            const int i = T * 8 + ii;
            ull w0 = cw1[i * 8 + 0], w1v = cw1[i * 8 + 1];
            ull w2v = cw1[i * 8 + 2], w3 = cw1[i * 8 + 3];
            ull w4 = cw1[i * 8 + 4], w5 = cw1[i * 8 + 5];
            ull w6 = cw1[i * 8 + 6], w7 = cw1[i * 8 + 7];
#pragma unroll
            for (int s = 0; s < SPT; s++) {
                float fv = (ii < 4) ? getc(lo[s], ii) : getc(hi[s], ii - 4);
                ull p = pack2(fv, fv);
                acc[s][0] = fma2(p, w0,  acc[s][0]);
                acc[s][1] = fma2(p, w1v, acc[s][1]);
                acc[s][2] = fma2(p, w2v, acc[s][2]);
                acc[s][3] = fma2(p, w3,  acc[s][3]);
                acc[s][4] = fma2(p, w4,  acc[s][4]);
                acc[s][5] = fma2(p, w5,  acc[s][5]);
                acc[s][6] = fma2(p, w6,  acc[s][6]);
                acc[s][7] = fma2(p, w7,  acc[s][7]);
            }
        }
    }

    // ---- dense features i = 24, 25 ----
#pragma unroll
    for (int ii = 0; ii < 2; ii++) {
        const int i = 24 + ii;
        ull w0 = cw1[i * 8 + 0], w1v = cw1[i * 8 + 1];
        ull w2v = cw1[i * 8 + 2], w3 = cw1[i * 8 + 3];
        ull w4 = cw1[i * 8 + 4], w5 = cw1[i * 8 + 5];
        ull w6 = cw1[i * 8 + 6], w7 = cw1[i * 8 + 7];
#pragma unroll
        for (int s = 0; s < SPT; s++) {
            float fv = (ii == 0) ? dn[s].x : dn[s].y;
            ull p = pack2(fv, fv);
            acc[s][0] = fma2(p, w0,  acc[s][0]);
            acc[s][1] = fma2(p, w1v, acc[s][1]);
            acc[s][2] = fma2(p, w2v, acc[s][2]);
            acc[s][3] = fma2(p, w3,  acc[s][3]);
            acc[s][4] = fma2(p, w4,  acc[s][4]);
            acc[s][5] = fma2(p, w5,  acc[s][5]);
            acc[s][6] = fma2(p, w6,  acc[s][6]);
            acc[s][7] = fma2(p, w7,  acc[s][7]);
        }
    }

    // ---- relu + layer 2 + sigmoid (w2/b2 via uniform LDG) ----
    float w2r[16];
#pragma unroll
    for (int k = 0; k < 16; k++) w2r[k] = __ldg(w2 + k);
    const float sb2v = __ldg(b2);
#pragma unroll
    for (int s = 0; s < SPT; s++) {
        float l = sb2v;
#pragma unroll
        for (int j = 0; j < 8; j++) {
            float h0, h1;
            unpack2(acc[s][j], h0, h1);
            l = fmaf(fmaxf(h0, 0.0f), w2r[2 * j],     l);
            l = fmaf(fmaxf(h1, 0.0f), w2r[2 * j + 1], l);
        }
        float e = __expf(-l);
        out[s0 + s * TPB] = __fdividef(1.0f, 1.0f + e);
    }
}

extern "C" void kernel_launch(void* const* d_in, const int* in_sizes, int n_in,
                              void* d_out, int out_size) {
    const int*    user_id = (const int*)d_in[0];
    const int*    item_id = (const int*)d_in[1];
    const int*    cat_id  = (const int*)d_in[2];
    const float2* dense   = (const float2*)d_in[3];
    const float4* user_t  = (const float4*)d_in[4];
    const float4* item_t  = (const float4*)d_in[5];
    const float4* cat_t   = (const float4*)d_in[6];
    const float*  w1      = (const float*)d_in[7];
    const float*  b1      = (const float*)d_in[8];
    const float*  w2      = (const float*)d_in[9];
    const float*  b2      = (const float*)d_in[10];
    float*        out     = (float*)d_out;

    // Single graph-capturable D2D memcpy node: only w1 lives in __constant__.
    cudaMemcpyToSymbolAsync(cw1, w1, 26 * 16 * sizeof(float), 0,
                            cudaMemcpyDeviceToDevice, 0);

    const int batch = in_sizes[0];
    const int per_block = TPB * SPT;
    const int blocks = (batch + per_block - 1) / per_block;

    dlrm_kernel<<<blocks, TPB>>>(user_id, item_id, cat_id, dense,
                                 user_t, item_t, cat_t,
                                 b1, w2, b2, out, batch);
}

// round 8
// speedup vs baseline: 1.6012x; 1.0029x over previous
#include <cuda_runtime.h>

#define TPB 128
#define SPT 4

typedef unsigned long long ull;

// w1 packed as 4-weight quads: cw1[i*4+q] = (w1[i][4q..4q+1], w1[i][4q+2..4q+3])
__constant__ ulonglong2 cw1[26 * 4];

__device__ __forceinline__ ull pack2(float lo, float hi) {
    ull r;
    asm("mov.b64 %0, {%1, %2};" : "=l"(r) : "f"(lo), "f"(hi));
    return r;
}
__device__ __forceinline__ void unpack2(ull v, float& lo, float& hi) {
    asm("mov.b64 {%0, %1}, %2;" : "=f"(lo), "=f"(hi) : "l"(v));
}
__device__ __forceinline__ ull fma2(ull a, ull b, ull c) {
    ull d;
    asm("fma.rn.f32x2 %0, %1, %2, %3;" : "=l"(d) : "l"(a), "l"(b), "l"(c));
    return d;
}
__device__ __forceinline__ float getc(float4 v, int k) {
    return (k == 0) ? v.x : (k == 1) ? v.y : (k == 2) ? v.z : v.w;
}

// Gather the 6 (table, sample-in-pair) groups for pair p. Cooperative pairwise:
// lanes 2k/2k+1 each fetch one 16B half of BOTH rows of the lane pair; every
// 128B line touched by exactly one instruction. Fetching lane reads the pair's
// ids directly from gmem (coalesced, 1 wavefront).
__device__ __forceinline__ void gather_pair(
    int p, int warpBase, int lane, int h,
    const int* __restrict__ user_id, const int* __restrict__ item_id,
    const int* __restrict__ cat_id,
    const float4* __restrict__ user_t, const float4* __restrict__ item_t,
    const float4* __restrict__ cat_t,
    float4* rA, float4* rB)
{
#pragma unroll
    for (int g = 0; g < 6; g++) {
        const int T = g >> 1, sp = g & 1;
        const int s = 2 * p + sp;
        const int* __restrict__ idp =
            (T == 0) ? user_id : (T == 1) ? item_id : cat_id;
        const float4* __restrict__ tab =
            (T == 0) ? user_t : (T == 1) ? item_t : cat_t;
        const int ge = warpBase + s * TPB + (lane & ~1);
        int idE = idp[ge];
        int idO = idp[ge + 1];
        rA[g] = tab[2 * (long)idE + h];
        rB[g] = tab[2 * (long)idO + h];
    }
}

// Full MLP for one sample pair; consumes rA/rB, writes 2 outputs.
__device__ __forceinline__ void compute_pair(
    const float4* rA, const float4* rB,   // [6], g = T*2 + sp
    float2 dn0, float2 dn1, bool odd,
    const float* __restrict__ b1, const float* __restrict__ w2,
    const float* __restrict__ b2,
    float* __restrict__ out, int o0, int o1)
{
    ull acc[2][8];
#pragma unroll
    for (int j = 0; j < 8; j++) {
        ull b = __ldg((const ull*)b1 + j);
        acc[0][j] = b;
        acc[1][j] = b;
    }

#pragma unroll
    for (int T = 0; T < 3; T++) {
        float4 lo[2], hi[2];
#pragma unroll
        for (int sp = 0; sp < 2; sp++) {
            const int g = T * 2 + sp;
            float4 send = odd ? rA[g] : rB[g];
            float4 own  = odd ? rB[g] : rA[g];
            float4 recv;
            recv.x = __shfl_xor_sync(0xFFFFFFFFu, send.x, 1);
            recv.y = __shfl_xor_sync(0xFFFFFFFFu, send.y, 1);
            recv.z = __shfl_xor_sync(0xFFFFFFFFu, send.z, 1);
            recv.w = __shfl_xor_sync(0xFFFFFFFFu, send.w, 1);
            lo[sp] = odd ? recv : own;
            hi[sp] = odd ? own  : recv;
        }
#pragma unroll
        for (int ii = 0; ii < 8; ii++) {
            const int i = T * 8 + ii;
            ulonglong2 q0 = cw1[i * 4 + 0];
            ulonglong2 q1 = cw1[i * 4 + 1];
            ulonglong2 q2 = cw1[i * 4 + 2];
            ulonglong2 q3 = cw1[i * 4 + 3];
#pragma unroll
            for (int sp = 0; sp < 2; sp++) {
                float fv = (ii < 4) ? getc(lo[sp], ii) : getc(hi[sp], ii - 4);
                ull pk = pack2(fv, fv);
                acc[sp][0] = fma2(pk, q0.x, acc[sp][0]);
                acc[sp][1] = fma2(pk, q0.y, acc[sp][1]);
                acc[sp][2] = fma2(pk, q1.x, acc[sp][2]);
                acc[sp][3] = fma2(pk, q1.y, acc[sp][3]);
                acc[sp][4] = fma2(pk, q2.x, acc[sp][4]);
                acc[sp][5] = fma2(pk, q2.y, acc[sp][5]);
                acc[sp][6] = fma2(pk, q3.x, acc[sp][6]);
                acc[sp][7] = fma2(pk, q3.y, acc[sp][7]);
            }
        }
    }

    // dense features i = 24, 25
#pragma unroll
    for (int ii = 0; ii < 2; ii++) {
        const int i = 24 + ii;
        ulonglong2 q0 = cw1[i * 4 + 0];
        ulonglong2 q1 = cw1[i * 4 + 1];
        ulonglong2 q2 = cw1[i * 4 + 2];
        ulonglong2 q3 = cw1[i * 4 + 3];
#pragma unroll
        for (int sp = 0; sp < 2; sp++) {
            float fv = (sp == 0) ? ((ii == 0) ? dn0.x : dn0.y)
                                 : ((ii == 0) ? dn1.x : dn1.y);
            ull pk = pack2(fv, fv);
            acc[sp][0] = fma2(pk, q0.x, acc[sp][0]);
            acc[sp][1] = fma2(pk, q0.y, acc[sp][1]);
            acc[sp][2] = fma2(pk, q1.x, acc[sp][2]);
            acc[sp][3] = fma2(pk, q1.y, acc[sp][3]);
            acc[sp][4] = fma2(pk, q2.x, acc[sp][4]);
            acc[sp][5] = fma2(pk, q2.y, acc[sp][5]);
            acc[sp][6] = fma2(pk, q3.x, acc[sp][6]);
            acc[sp][7] = fma2(pk, q3.y, acc[sp][7]);
        }
    }

    // relu + layer 2 + sigmoid (w2/b2 uniform, L1-hot)
    const float sb2 = __ldg(b2);
#pragma unroll
    for (int sp = 0; sp < 2; sp++) {
        float l = sb2;
#pragma unroll
        for (int j = 0; j < 8; j++) {
            float h0, h1;
            unpack2(acc[sp][j], h0, h1);
            l = fmaf(fmaxf(h0, 0.0f), __ldg(w2 + 2 * j),     l);
            l = fmaf(fmaxf(h1, 0.0f), __ldg(w2 + 2 * j + 1), l);
        }
        float e = __expf(-l);
        out[sp == 0 ? o0 : o1] = __fdividef(1.0f, 1.0f + e);
    }
}

__global__ __launch_bounds__(TPB, 4) void dlrm_kernel(
    const int*    __restrict__ user_id,
    const int*    __restrict__ item_id,
    const int*    __restrict__ cat_id,
    const float2* __restrict__ dense,
    const float4* __restrict__ user_t,   // [NUM_USERS, 8] as [., 2] float4
    const float4* __restrict__ item_t,
    const float4* __restrict__ cat_t,
    const float*  __restrict__ b1,
    const float*  __restrict__ w2,
    const float*  __restrict__ b2,
    float*        __restrict__ out,
    int batch)
{
    const int lane = threadIdx.x & 31;
    const int h    = lane & 1;
    const bool odd = (h != 0);

    const int blockBase = blockIdx.x * (TPB * SPT);
    const int s0 = blockBase + threadIdx.x;
    if (s0 >= batch) return;  // never taken: batch % (TPB*SPT) == 0
    const int warpBase = blockBase + (threadIdx.x & ~31);

    // Phase 0+1: issue all 24 row loads (full MLP depth preserved)
    float4 aA[6], aB[6];
    gather_pair(0, warpBase, lane, h, user_id, item_id, cat_id,
                user_t, item_t, cat_t, aA, aB);
    float4 bA[6], bB[6];
    gather_pair(1, warpBase, lane, h, user_id, item_id, cat_id,
                user_t, item_t, cat_t, bA, bB);

    // Pair 0: compute fully (frees aA/aB + its accs), pair-1 loads in flight
    {
        float2 d0 = dense[s0];
        float2 d1 = dense[s0 + TPB];
        compute_pair(aA, aB, d0, d1, odd, b1, w2, b2, out, s0, s0 + TPB);
    }
    // Pair 1
    {
        float2 d2 = dense[s0 + 2 * TPB];
        float2 d3 = dense[s0 + 3 * TPB];
        compute_pair(bA, bB, d2, d3, odd, b1, w2, b2, out,
                     s0 + 2 * TPB, s0 + 3 * TPB);
    }
}

extern "C" void kernel_launch(void* const* d_in, const int* in_sizes, int n_in,
                              void* d_out, int out_size) {
    const int*    user_id = (const int*)d_in[0];
    const int*    item_id = (const int*)d_in[1];
    const int*    cat_id  = (const int*)d_in[2];
    const float2* dense   = (const float2*)d_in[3];
    const float4* user_t  = (const float4*)d_in[4];
    const float4* item_t  = (const float4*)d_in[5];
    const float4* cat_t   = (const float4*)d_in[6];
    const float*  w1      = (const float*)d_in[7];
    const float*  b1      = (const float*)d_in[8];
    const float*  w2      = (const float*)d_in[9];
    const float*  b2      = (const float*)d_in[10];
    float*        out     = (float*)d_out;

    // Single graph-capturable D2D memcpy node (byte layout of cw1 == w1).
    cudaMemcpyToSymbolAsync(cw1, w1, 26 * 16 * sizeof(float), 0,
                            cudaMemcpyDeviceToDevice, 0);

    const int batch = in_sizes[0];
    const int per_block = TPB * SPT;
    const int blocks = (batch + per_block - 1) / per_block;

    dlrm_kernel<<<blocks, TPB>>>(user_id, item_id, cat_id, dense,
                                 user_t, item_t, cat_t,
                                 b1, w2, b2, out, batch);
}

// round 9
// speedup vs baseline: 1.7705x; 1.1057x over previous
#include <cuda_runtime.h>

#define TPB 128
#define SPT 4

typedef unsigned long long ull;

// w1 packed as 4-weight quads: cw1[i*4+q] = (w1[i][4q+0..1], w1[i][4q+2..3])
__constant__ ulonglong2 cw1[26 * 4];

__device__ __forceinline__ ull pack2(float lo, float hi) {
    ull r;
    asm("mov.b64 %0, {%1, %2};" : "=l"(r) : "f"(lo), "f"(hi));
    return r;
}
__device__ __forceinline__ void unpack2(ull v, float& lo, float& hi) {
    asm("mov.b64 {%0, %1}, %2;" : "=f"(lo), "=f"(hi) : "l"(v));
}
__device__ __forceinline__ ull fma2(ull a, ull b, ull c) {
    ull d;
    asm("fma.rn.f32x2 %0, %1, %2, %3;" : "=l"(d) : "l"(a), "l"(b), "l"(c));
    return d;
}
__device__ __forceinline__ float getc(float4 v, int k) {
    return (k == 0) ? v.x : (k == 1) ? v.y : (k == 2) ? v.z : v.w;
}

// Gather one table's rows for all 4 samples. Cooperative pairwise: lanes
// 2k/2k+1 each fetch one 16B half of BOTH rows of the lane pair; every 128B
// line touched by exactly one instruction. Pair ids fetched as one int2.
__device__ __forceinline__ void gather_T(
    int warpBase, int lane, int h,
    const int* __restrict__ idp, const float4* __restrict__ tab,
    float4 (&rA)[4], float4 (&rB)[4])
{
#pragma unroll
    for (int s = 0; s < 4; s++) {
        const int ge = warpBase + s * TPB + (lane & ~1);
        int2 id2 = *(const int2*)(idp + ge);     // LDG.64, coalesced
        rA[s] = tab[2 * (long)id2.x + h];
        rB[s] = tab[2 * (long)id2.y + h];
    }
}

// Exchange halves within lane pairs, then FMA this table's 8 features into
// all 4 samples' accumulators. Weights loaded ONCE per i (shared by samples).
__device__ __forceinline__ void process_T(
    int T, bool odd, const float4 (&rA)[4], const float4 (&rB)[4],
    ull (&acc)[4][8])
{
    float4 lo[4], hi[4];
#pragma unroll
    for (int s = 0; s < 4; s++) {
        float4 send = odd ? rA[s] : rB[s];
        float4 own  = odd ? rB[s] : rA[s];
        float4 recv;
        recv.x = __shfl_xor_sync(0xFFFFFFFFu, send.x, 1);
        recv.y = __shfl_xor_sync(0xFFFFFFFFu, send.y, 1);
        recv.z = __shfl_xor_sync(0xFFFFFFFFu, send.z, 1);
        recv.w = __shfl_xor_sync(0xFFFFFFFFu, send.w, 1);
        lo[s] = odd ? recv : own;
        hi[s] = odd ? own  : recv;
    }
#pragma unroll
    for (int ii = 0; ii < 8; ii++) {
        const int i = T * 8 + ii;
        ulonglong2 q0 = cw1[i * 4 + 0];
        ulonglong2 q1 = cw1[i * 4 + 1];
        ulonglong2 q2 = cw1[i * 4 + 2];
        ulonglong2 q3 = cw1[i * 4 + 3];
#pragma unroll
        for (int s = 0; s < 4; s++) {
            float fv = (ii < 4) ? getc(lo[s], ii) : getc(hi[s], ii - 4);
            ull pk = pack2(fv, fv);
            acc[s][0] = fma2(pk, q0.x, acc[s][0]);
            acc[s][1] = fma2(pk, q0.y, acc[s][1]);
            acc[s][2] = fma2(pk, q1.x, acc[s][2]);
            acc[s][3] = fma2(pk, q1.y, acc[s][3]);
            acc[s][4] = fma2(pk, q2.x, acc[s][4]);
            acc[s][5] = fma2(pk, q2.y, acc[s][5]);
            acc[s][6] = fma2(pk, q3.x, acc[s][6]);
            acc[s][7] = fma2(pk, q3.y, acc[s][7]);
        }
    }
}

__global__ __launch_bounds__(TPB, 4) void dlrm_kernel(
    const int*    __restrict__ user_id,
    const int*    __restrict__ item_id,
    const int*    __restrict__ cat_id,
    const float2* __restrict__ dense,
    const float4* __restrict__ user_t,   // [NUM_USERS, 8] as [., 2] float4
    const float4* __restrict__ item_t,
    const float4* __restrict__ cat_t,
    const float*  __restrict__ b1,
    const float*  __restrict__ w2,
    const float*  __restrict__ b2,
    float*        __restrict__ out,
    int batch)
{
    const int lane = threadIdx.x & 31;
    const int h    = lane & 1;
    const bool odd = (h != 0);

    const int blockBase = blockIdx.x * (TPB * SPT);
    const int s0 = blockBase + threadIdx.x;
    if (s0 >= batch) return;  // never taken: batch % (TPB*SPT) == 0
    const int warpBase = blockBase + (threadIdx.x & ~31);

    // Double-buffered gather: user(T0) and item(T1) in flight up front.
    float4 A0[4], B0[4], A1[4], B1[4];
    gather_T(warpBase, lane, h, user_id, user_t, A0, B0);
    gather_T(warpBase, lane, h, item_id, item_t, A1, B1);

    // Accumulators + dense features FIRST (i order is irrelevant for the sum;
    // dn registers die before the liveness peak).
    ull acc[4][8];
#pragma unroll
    for (int j = 0; j < 8; j++) {
        ull b = __ldg((const ull*)b1 + j);
#pragma unroll
        for (int s = 0; s < 4; s++) acc[s][j] = b;
    }
    {
        float2 dn[4];
#pragma unroll
        for (int s = 0; s < 4; s++) dn[s] = dense[s0 + s * TPB];
#pragma unroll
        for (int ii = 0; ii < 2; ii++) {
            const int i = 24 + ii;
            ulonglong2 q0 = cw1[i * 4 + 0];
            ulonglong2 q1 = cw1[i * 4 + 1];
            ulonglong2 q2 = cw1[i * 4 + 2];
            ulonglong2 q3 = cw1[i * 4 + 3];
#pragma unroll
            for (int s = 0; s < 4; s++) {
                float fv = (ii == 0) ? dn[s].x : dn[s].y;
                ull pk = pack2(fv, fv);
                acc[s][0] = fma2(pk, q0.x, acc[s][0]);
                acc[s][1] = fma2(pk, q0.y, acc[s][1]);
                acc[s][2] = fma2(pk, q1.x, acc[s][2]);
                acc[s][3] = fma2(pk, q1.y, acc[s][3]);
                acc[s][4] = fma2(pk, q2.x, acc[s][4]);
                acc[s][5] = fma2(pk, q2.y, acc[s][5]);
                acc[s][6] = fma2(pk, q3.x, acc[s][6]);
                acc[s][7] = fma2(pk, q3.y, acc[s][7]);
            }
        }
    }

    // T0 compute; then reuse its buffers for cat(T2) gather, covered by T1.
    process_T(0, odd, A0, B0, acc);
    gather_T(warpBase, lane, h, cat_id, cat_t, A0, B0);
    process_T(1, odd, A1, B1, acc);
    process_T(2, odd, A0, B0, acc);

    // ---- relu + layer 2 + sigmoid (w2/b2 uniform, L1-hot) ----
    const float sb2 = __ldg(b2);
#pragma unroll
    for (int s = 0; s < 4; s++) {
        float l = sb2;
#pragma unroll
        for (int j = 0; j < 8; j++) {
            float h0, h1;
            unpack2(acc[s][j], h0, h1);
            l = fmaf(fmaxf(h0, 0.0f), __ldg(w2 + 2 * j),     l);
            l = fmaf(fmaxf(h1, 0.0f), __ldg(w2 + 2 * j + 1), l);
        }
        float e = __expf(-l);
        out[s0 + s * TPB] = __fdividef(1.0f, 1.0f + e);
    }
}

extern "C" void kernel_launch(void* const* d_in, const int* in_sizes, int n_in,
                              void* d_out, int out_size) {
    const int*    user_id = (const int*)d_in[0];
    const int*    item_id = (const int*)d_in[1];
    const int*    cat_id  = (const int*)d_in[2];
    const float2* dense   = (const float2*)d_in[3];
    const float4* user_t  = (const float4*)d_in[4];
    const float4* item_t  = (const float4*)d_in[5];
    const float4* cat_t   = (const float4*)d_in[6];
    const float*  w1      = (const float*)d_in[7];
    const float*  b1      = (const float*)d_in[8];
    const float*  w2      = (const float*)d_in[9];
    const float*  b2      = (const float*)d_in[10];
    float*        out     = (float*)d_out;

    // Single graph-capturable D2D memcpy node (byte layout of cw1 == w1).
    cudaMemcpyToSymbolAsync(cw1, w1, 26 * 16 * sizeof(float), 0,
                            cudaMemcpyDeviceToDevice, 0);

    const int batch = in_sizes[0];
    const int per_block = TPB * SPT;
    const int blocks = (batch + per_block - 1) / per_block;

    dlrm_kernel<<<blocks, TPB>>>(user_id, item_id, cat_id, dense,
                                 user_t, item_t, cat_t,
                                 b1, w2, b2, out, batch);
}

// round 10
// speedup vs baseline: 1.8008x; 1.0171x over previous
#include <cuda_runtime.h>

#define TPB 128
#define SPT 4

typedef unsigned long long ull;

// w1 packed as 4-weight quads: cw1[i*4+q] = (w1[i][4q+0..1], w1[i][4q+2..3])
__constant__ ulonglong2 cw1[26 * 4];

__device__ __forceinline__ ull pack2(float lo, float hi) {
    ull r;
    asm("mov.b64 %0, {%1, %2};" : "=l"(r) : "f"(lo), "f"(hi));
    return r;
}
__device__ __forceinline__ void unpack2(ull v, float& lo, float& hi) {
    asm("mov.b64 {%0, %1}, %2;" : "=f"(lo), "=f"(hi) : "l"(v));
}
__device__ __forceinline__ ull fma2(ull a, ull b, ull c) {
    ull d;
    asm("fma.rn.f32x2 %0, %1, %2, %3;" : "=l"(d) : "l"(a), "l"(b), "l"(c));
    return d;
}
__device__ __forceinline__ float getc(float4 v, int k) {
    return (k == 0) ? v.x : (k == 1) ? v.y : (k == 2) ? v.z : v.w;
}

// Gather one table's rows for all 4 samples. Cooperative pairwise: lanes
// 2k/2k+1 each fetch one 16B half of BOTH rows of the lane pair; every 128B
// line touched by exactly one instruction. Pair ids fetched as one int2 with
// evict-streaming (ids have zero reuse; keep them out of L2's table set).
__device__ __forceinline__ void gather_T(
    int warpBase, int lane, int h,
    const int* __restrict__ idp, const float4* __restrict__ tab,
    float4 (&rA)[4], float4 (&rB)[4])
{
#pragma unroll
    for (int s = 0; s < 4; s++) {
        const int ge = warpBase + s * TPB + (lane & ~1);
        int2 id2 = __ldcs((const int2*)(idp + ge));   // LDG.64.STREAM, coalesced
        rA[s] = tab[2 * (long)id2.x + h];             // tables: normal caching
        rB[s] = tab[2 * (long)id2.y + h];
    }
}

// Exchange halves within lane pairs, then FMA this table's 8 features into
// all 4 samples' accumulators. Weights loaded ONCE per i (shared by samples).
__device__ __forceinline__ void process_T(
    int T, bool odd, const float4 (&rA)[4], const float4 (&rB)[4],
    ull (&acc)[4][8])
{
    float4 lo[4], hi[4];
#pragma unroll
    for (int s = 0; s < 4; s++) {
        float4 send = odd ? rA[s] : rB[s];
        float4 own  = odd ? rB[s] : rA[s];
        float4 recv;
        recv.x = __shfl_xor_sync(0xFFFFFFFFu, send.x, 1);
        recv.y = __shfl_xor_sync(0xFFFFFFFFu, send.y, 1);
        recv.z = __shfl_xor_sync(0xFFFFFFFFu, send.z, 1);
        recv.w = __shfl_xor_sync(0xFFFFFFFFu, send.w, 1);
        lo[s] = odd ? recv : own;
        hi[s] = odd ? own  : recv;
    }
#pragma unroll
    for (int ii = 0; ii < 8; ii++) {
        const int i = T * 8 + ii;
        ulonglong2 q0 = cw1[i * 4 + 0];
        ulonglong2 q1 = cw1[i * 4 + 1];
        ulonglong2 q2 = cw1[i * 4 + 2];
        ulonglong2 q3 = cw1[i * 4 + 3];
#pragma unroll
        for (int s = 0; s < 4; s++) {
            float fv = (ii < 4) ? getc(lo[s], ii) : getc(hi[s], ii - 4);
            ull pk = pack2(fv, fv);
            acc[s][0] = fma2(pk, q0.x, acc[s][0]);
            acc[s][1] = fma2(pk, q0.y, acc[s][1]);
            acc[s][2] = fma2(pk, q1.x, acc[s][2]);
            acc[s][3] = fma2(pk, q1.y, acc[s][3]);
            acc[s][4] = fma2(pk, q2.x, acc[s][4]);
            acc[s][5] = fma2(pk, q2.y, acc[s][5]);
            acc[s][6] = fma2(pk, q3.x, acc[s][6]);
            acc[s][7] = fma2(pk, q3.y, acc[s][7]);
        }
    }
}

__global__ __launch_bounds__(TPB, 4) void dlrm_kernel(
    const int*    __restrict__ user_id,
    const int*    __restrict__ item_id,
    const int*    __restrict__ cat_id,
    const float2* __restrict__ dense,
    const float4* __restrict__ user_t,   // [NUM_USERS, 8] as [., 2] float4
    const float4* __restrict__ item_t,
    const float4* __restrict__ cat_t,
    const float*  __restrict__ b1,
    const float*  __restrict__ w2,
    const float*  __restrict__ b2,
    float*        __restrict__ out,
    int batch)
{
    const int lane = threadIdx.x & 31;
    const int h    = lane & 1;
    const bool odd = (h != 0);

    const int blockBase = blockIdx.x * (TPB * SPT);
    const int s0 = blockBase + threadIdx.x;
    if (s0 >= batch) return;  // never taken: batch % (TPB*SPT) == 0
    const int warpBase = blockBase + (threadIdx.x & ~31);

    // Double-buffered gather: user(T0) and item(T1) in flight up front.
    float4 A0[4], B0[4], A1[4], B1[4];
    gather_T(warpBase, lane, h, user_id, user_t, A0, B0);
    gather_T(warpBase, lane, h, item_id, item_t, A1, B1);

    // Accumulators + dense features FIRST (i order is irrelevant for the sum;
    // dn registers die before the liveness peak). Dense is a pure stream ->
    // evict-first.
    ull acc[4][8];
#pragma unroll
    for (int j = 0; j < 8; j++) {
        ull b = __ldg((const ull*)b1 + j);
#pragma unroll
        for (int s = 0; s < 4; s++) acc[s][j] = b;
    }
    {
        float2 dn[4];
#pragma unroll
        for (int s = 0; s < 4; s++) dn[s] = __ldcs(&dense[s0 + s * TPB]);
#pragma unroll
        for (int ii = 0; ii < 2; ii++) {
            const int i = 24 + ii;
            ulonglong2 q0 = cw1[i * 4 + 0];
            ulonglong2 q1 = cw1[i * 4 + 1];
            ulonglong2 q2 = cw1[i * 4 + 2];
            ulonglong2 q3 = cw1[i * 4 + 3];
#pragma unroll
            for (int s = 0; s < 4; s++) {
                float fv = (ii == 0) ? dn[s].x : dn[s].y;
                ull pk = pack2(fv, fv);
                acc[s][0] = fma2(pk, q0.x, acc[s][0]);
                acc[s][1] = fma2(pk, q0.y, acc[s][1]);
                acc[s][2] = fma2(pk, q1.x, acc[s][2]);
                acc[s][3] = fma2(pk, q1.y, acc[s][3]);
                acc[s][4] = fma2(pk, q2.x, acc[s][4]);
                acc[s][5] = fma2(pk, q2.y, acc[s][5]);
                acc[s][6] = fma2(pk, q3.x, acc[s][6]);
                acc[s][7] = fma2(pk, q3.y, acc[s][7]);
            }
        }
    }

    // T0 compute; then reuse its buffers for cat(T2) gather, covered by T1.
    process_T(0, odd, A0, B0, acc);
    gather_T(warpBase, lane, h, cat_id, cat_t, A0, B0);
    process_T(1, odd, A1, B1, acc);
    process_T(2, odd, A0, B0, acc);

    // ---- relu + layer 2 + sigmoid (w2/b2 uniform, L1-hot) ----
    const float sb2 = __ldg(b2);
#pragma unroll
    for (int s = 0; s < 4; s++) {
        float l = sb2;
#pragma unroll
        for (int j = 0; j < 8; j++) {
            float h0, h1;
            unpack2(acc[s][j], h0, h1);
            l = fmaf(fmaxf(h0, 0.0f), __ldg(w2 + 2 * j),     l);
            l = fmaf(fmaxf(h1, 0.0f), __ldg(w2 + 2 * j + 1), l);
        }
        float e = __expf(-l);
        __stcs(&out[s0 + s * TPB], __fdividef(1.0f, 1.0f + e));  // stream out
    }
}

extern "C" void kernel_launch(void* const* d_in, const int* in_sizes, int n_in,
                              void* d_out, int out_size) {
    const int*    user_id = (const int*)d_in[0];
    const int*    item_id = (const int*)d_in[1];
    const int*    cat_id  = (const int*)d_in[2];
    const float2* dense   = (const float2*)d_in[3];
    const float4* user_t  = (const float4*)d_in[4];
    const float4* item_t  = (const float4*)d_in[5];
    const float4* cat_t   = (const float4*)d_in[6];
    const float*  w1      = (const float*)d_in[7];
    const float*  b1      = (const float*)d_in[8];
    const float*  w2      = (const float*)d_in[9];
    const float*  b2      = (const float*)d_in[10];
    float*        out     = (float*)d_out;

    // Single graph-capturable D2D memcpy node (byte layout of cw1 == w1).
    cudaMemcpyToSymbolAsync(cw1, w1, 26 * 16 * sizeof(float), 0,
                            cudaMemcpyDeviceToDevice, 0);

    const int batch = in_sizes[0];
    const int per_block = TPB * SPT;
    const int blocks = (batch + per_block - 1) / per_block;

    dlrm_kernel<<<blocks, TPB>>>(user_id, item_id, cat_id, dense,
                                 user_t, item_t, cat_t,
                                 b1, w2, b2, out, batch);
}